// round 8
// baseline (speedup 1.0000x reference)
#include <cuda_runtime.h>
#include <cstdint>

#define NN 50000
#define NE 300000

// ---------------- scratch (static __device__ arrays; no allocation) ----------------
__device__ float g_support[NN * 64];   // L1: x @ W1
__device__ float g_agg[NN * 256];      // aggregation buffer (accumulated across L4-L6)
__device__ float g_l1[NN * 64];
__device__ float g_l2[NN * 128];
__device__ float g_l3[NN * 256];
__device__ float g_l4[NN * 256];
__device__ float g_l5[NN * 256];

// ---------------- packed f32x2 FMA (sm_100+): d = a*b + d, lanewise on 2 floats ----------------
__device__ __forceinline__ void ffma2(uint64_t& d, uint64_t a, uint64_t b)
{
    asm("fma.rn.f32x2 %0, %1, %2, %0;" : "+l"(d) : "l"(a), "l"(b));
}
__device__ __forceinline__ uint64_t pack_dup(float f)
{
    uint64_t r;
    asm("mov.b64 %0, {%1, %1};" : "=l"(r) : "r"(__float_as_uint(f)));
    return r;
}

// ---------------- big GEMM: 128x128 tile, 8x8 microtile, f32x2 FMA ----------------
// Double-buffered smem, software-pipelined global prefetch: ONE barrier per k-tile.
// C[M,N] = A[M,K] @ B[K,N] (+bias+relu if fuse). K mult of 16, N mult of 128.
__global__ __launch_bounds__(256)
void gemm128_kernel(const float* __restrict__ A, const float* __restrict__ B,
                    const float* __restrict__ bias, float* __restrict__ C,
                    int M, int K, int N, int fuse)
{
    __shared__ float As[2][16][132];   // [buf][k][m] (transposed)
    __shared__ float Bs[2][16][132];   // [buf][k][n]

    const int tid = threadIdx.x;
    const int m0  = blockIdx.y * 128;
    const int n0  = blockIdx.x * 128;
    const int tx  = tid & 15;       // n-dim thread coord
    const int ty  = tid >> 4;       // m-dim thread coord

    const int a_m = tid >> 1;            // 0..127
    const int a_k = (tid & 1) * 8;       // 0 or 8
    const int b_k = tid >> 4;            // 0..15
    const int b_n = (tid & 15) * 8;      // 0..120

    const bool a_valid = (m0 + a_m) < M;
    const float* a_ptr = A + (long)(m0 + a_m) * K + a_k;
    const float* b_ptr = B + (long)b_k * N + n0 + b_n;

    uint64_t acc2[8][4];
    #pragma unroll
    for (int i = 0; i < 8; i++)
        #pragma unroll
        for (int j = 0; j < 4; j++) acc2[i][j] = 0ull;

    // prologue: prefetch tile 0 into registers
    float4 pa0 = make_float4(0.f,0.f,0.f,0.f), pa1 = make_float4(0.f,0.f,0.f,0.f);
    float4 pb0, pb1;
    if (a_valid) {
        pa0 = *(const float4*)(a_ptr);
        pa1 = *(const float4*)(a_ptr + 4);
    }
    pb0 = *(const float4*)(b_ptr);
    pb1 = *(const float4*)(b_ptr + 4);

    int buf = 0;
    for (int k0 = 0; k0 < K; k0 += 16) {
        // commit prefetched tile into smem[buf]
        As[buf][a_k + 0][a_m] = pa0.x;  As[buf][a_k + 1][a_m] = pa0.y;
        As[buf][a_k + 2][a_m] = pa0.z;  As[buf][a_k + 3][a_m] = pa0.w;
        As[buf][a_k + 4][a_m] = pa1.x;  As[buf][a_k + 5][a_m] = pa1.y;
        As[buf][a_k + 6][a_m] = pa1.z;  As[buf][a_k + 7][a_m] = pa1.w;
        *(float4*)&Bs[buf][b_k][b_n]     = pb0;
        *(float4*)&Bs[buf][b_k][b_n + 4] = pb1;
        __syncthreads();   // the ONLY barrier per tile

        // prefetch tile t+1 (LDGs drain behind the FFMA block)
        if (k0 + 16 < K) {
            const float* ap = a_ptr + (k0 + 16);
            const float* bp = b_ptr + (long)(k0 + 16) * N;
            if (a_valid) {
                pa0 = *(const float4*)(ap);
                pa1 = *(const float4*)(ap + 4);
            }
            pb0 = *(const float4*)(bp);
            pb1 = *(const float4*)(bp + 4);
        }

        #pragma unroll
        for (int k = 0; k < 16; k++) {
            float4 a0 = *(const float4*)&As[buf][k][ty * 4];
            float4 a1 = *(const float4*)&As[buf][k][64 + ty * 4];
            ulonglong2 b0 = *(const ulonglong2*)&Bs[buf][k][tx * 4];
            ulonglong2 b1 = *(const ulonglong2*)&Bs[buf][k][64 + tx * 4];
            uint64_t bb[4] = {b0.x, b0.y, b1.x, b1.y};
            float af[8] = {a0.x, a0.y, a0.z, a0.w, a1.x, a1.y, a1.z, a1.w};
            #pragma unroll
            for (int i = 0; i < 8; i++) {
                uint64_t ai = pack_dup(af[i]);
                #pragma unroll
                for (int j = 0; j < 4; j++)
                    ffma2(acc2[i][j], ai, bb[j]);
            }
        }
        buf ^= 1;   // next store targets the other buffer; no trailing barrier needed
    }

    // epilogue
    #pragma unroll
    for (int i = 0; i < 8; i++) {
        int row = m0 + ((i < 4) ? (ty * 4 + i) : (64 + ty * 4 + i - 4));
        if (row >= M) continue;
        #pragma unroll
        for (int h = 0; h < 2; h++) {
            int col = n0 + ((h == 0) ? (tx * 4) : (64 + tx * 4));
            uint32_t lo0 = (uint32_t)(acc2[i][2*h + 0] & 0xFFFFFFFFu);
            uint32_t hi0 = (uint32_t)(acc2[i][2*h + 0] >> 32);
            uint32_t lo1 = (uint32_t)(acc2[i][2*h + 1] & 0xFFFFFFFFu);
            uint32_t hi1 = (uint32_t)(acc2[i][2*h + 1] >> 32);
            float4 o = make_float4(__uint_as_float(lo0), __uint_as_float(hi0),
                                   __uint_as_float(lo1), __uint_as_float(hi1));
            if (fuse) {
                float4 bs = *(const float4*)(bias + col);
                o.x = fmaxf(o.x + bs.x, 0.f);
                o.y = fmaxf(o.y + bs.y, 0.f);
                o.z = fmaxf(o.z + bs.z, 0.f);
                o.w = fmaxf(o.w + bs.w, 0.f);
            }
            *(float4*)(C + (long)row * N + col) = o;
        }
    }
}

// ---------------- small GEMM (layer 1): 64x64 tile, 4x4 microtile ----------------
__global__ void gemm64_kernel(const float* __restrict__ A, const float* __restrict__ B,
                              const float* __restrict__ bias, float* __restrict__ C,
                              int M, int K, int N, int fuse)
{
    __shared__ float As[16][68];
    __shared__ float Bs[16][68];

    const int tid = threadIdx.x;
    const int m0  = blockIdx.y * 64;
    const int n0  = blockIdx.x * 64;
    const int tx  = tid & 15;
    const int ty  = tid >> 4;

    const int a_m = tid >> 2;
    const int a_k = (tid & 3) * 4;
    const int b_k = tid >> 4;
    const int b_n = (tid & 15) * 4;

    float acc[4][4];
    #pragma unroll
    for (int i = 0; i < 4; i++)
        #pragma unroll
        for (int j = 0; j < 4; j++) acc[i][j] = 0.f;

    for (int k0 = 0; k0 < K; k0 += 16) {
        {
            int row = m0 + a_m;
            float4 av = make_float4(0.f, 0.f, 0.f, 0.f);
            if (row < M)
                av = *(const float4*)(A + (long)row * K + k0 + a_k);
            As[a_k + 0][a_m] = av.x;
            As[a_k + 1][a_m] = av.y;
            As[a_k + 2][a_m] = av.z;
            As[a_k + 3][a_m] = av.w;
        }
        {
            float4 bv = *(const float4*)(B + (long)(k0 + b_k) * N + n0 + b_n);
            *(float4*)&Bs[b_k][b_n] = bv;
        }
        __syncthreads();

        #pragma unroll
        for (int k = 0; k < 16; k++) {
            float4 a = *(const float4*)&As[k][ty * 4];
            float4 b = *(const float4*)&Bs[k][tx * 4];
            float ar[4] = {a.x, a.y, a.z, a.w};
            float br[4] = {b.x, b.y, b.z, b.w};
            #pragma unroll
            for (int i = 0; i < 4; i++)
                #pragma unroll
                for (int j = 0; j < 4; j++)
                    acc[i][j] += ar[i] * br[j];
        }
        __syncthreads();
    }

    #pragma unroll
    for (int i = 0; i < 4; i++) {
        int row = m0 + ty * 4 + i;
        if (row >= M) continue;
        float4 o;
        float* po = (float*)&o;
        #pragma unroll
        for (int j = 0; j < 4; j++) {
            float v = acc[i][j];
            if (fuse) {
                v += __ldg(&bias[n0 + tx * 4 + j]);
                v = fmaxf(v, 0.f);
            }
            po[j] = v;
        }
        *(float4*)(C + (long)row * N + n0 + tx * 4) = o;
    }
}

// ---------------- vectorized global reduction: one 16B red per chunk ----------------
__device__ __forceinline__ void red_add_v4(float* addr, float4 v)
{
    asm volatile("red.global.add.v4.f32 [%0], {%1, %2, %3, %4};"
                 :: "l"(addr), "f"(v.x), "f"(v.y), "f"(v.z), "f"(v.w)
                 : "memory");
}

// ---------------- edge scatter: agg[dst] += s0[src] * w (single source) ----------------
// Compile-time: one thread per (edge, NF-float span). D = (1<<SHIFT)*NF.
// Loads issued together (MLP=NF/4), then reds. total = NE << SHIFT.
template<int SHIFT, int NF>
__global__ void scatter_kernel(const float* __restrict__ s0,
                               const int* __restrict__ src, const int* __restrict__ dst,
                               const float* __restrict__ w,
                               float* __restrict__ agg, int total)
{
    constexpr int D = (1 << SHIFT) * NF;
    int idx = blockIdx.x * blockDim.x + threadIdx.x;
    if (idx >= total) return;
    int e = idx >> SHIFT;
    int c = (idx & ((1 << SHIFT) - 1)) * NF;

    int s = __ldg(&src[e]);
    int d = __ldg(&dst[e]);
    float wt = __ldg(&w[e]);

    const float* ps = s0 + (long)s * D + c;
    float4 v[NF / 4];
    #pragma unroll
    for (int i = 0; i < NF / 4; i++)
        v[i] = *(const float4*)(ps + 4 * i);   // independent LDG.128s, batched

    #pragma unroll
    for (int i = 0; i < NF / 4; i++) {
        v[i].x *= wt; v[i].y *= wt; v[i].z *= wt; v[i].w *= wt;
    }

    float* pa = agg + (long)d * D + c;
    #pragma unroll
    for (int i = 0; i < NF / 4; i++)
        red_add_v4(pa + 4 * i, v[i]);
}

// ---------------- bias + relu, and re-zero the source buffer in the same pass ----------------
// out = relu(in + bias); in := 0. Sole reader of `in` at this point, so safe.
__global__ void bias_relu_zero_kernel(float* __restrict__ in, const float* __restrict__ bias,
                                      float* __restrict__ out, int Dq, int total)
{
    int idx = blockIdx.x * blockDim.x + threadIdx.x;
    if (idx >= total) return;
    int c = idx & (Dq - 1);
    float4 v = ((const float4*)in)[idx];
    float4 b = ((const float4*)bias)[c];
    v.x = fmaxf(v.x + b.x, 0.f);
    v.y = fmaxf(v.y + b.y, 0.f);
    v.z = fmaxf(v.z + b.z, 0.f);
    v.w = fmaxf(v.w + b.w, 0.f);
    ((float4*)out)[idx] = v;
    ((float4*)in)[idx] = make_float4(0.f, 0.f, 0.f, 0.f);
}

// ---------------- launch ----------------
extern "C" void kernel_launch(void* const* d_in, const int* in_sizes, int n_in,
                              void* d_out, int out_size)
{
    const float* x    = (const float*)d_in[0];
    const int*   esrc = (const int*)d_in[1];
    const int*   edst = (const int*)d_in[2];
    const float* ew   = (const float*)d_in[3];
    const float* W1 = (const float*)d_in[4];  const float* b1 = (const float*)d_in[5];
    const float* W2 = (const float*)d_in[6];  const float* b2 = (const float*)d_in[7];
    const float* W3 = (const float*)d_in[8];  const float* b3 = (const float*)d_in[9];
    const float* W4 = (const float*)d_in[10]; const float* b4 = (const float*)d_in[11];
    const float* W5 = (const float*)d_in[12]; const float* b5 = (const float*)d_in[13];
    const float* W6 = (const float*)d_in[14]; const float* b6 = (const float*)d_in[15];
    float* out = (float*)d_out;

    float *support, *agg, *l1, *l2, *l3, *l4, *l5;
    cudaGetSymbolAddress((void**)&support, g_support);
    cudaGetSymbolAddress((void**)&agg, g_agg);
    cudaGetSymbolAddress((void**)&l1, g_l1);
    cudaGetSymbolAddress((void**)&l2, g_l2);
    cudaGetSymbolAddress((void**)&l3, g_l3);
    cudaGetSymbolAddress((void**)&l4, g_l4);
    cudaGetSymbolAddress((void**)&l5, g_l5);

    const int MB64  = (NN + 63) / 64;    // 782
    const int MB128 = (NN + 127) / 128;  // 391

    // ---- Layer 1 (GEMM first: scatter only 64 channels): support = x @ W1 ----
    gemm64_kernel<<<dim3(1, MB64), 256>>>(x, W1, nullptr, support, NN, 128, 64, 0);
    cudaMemsetAsync(agg, 0, (size_t)NN * 64 * sizeof(float));
    {
        int total = NE << 3;   // D=64: SHIFT=3, NF=8
        scatter_kernel<3, 8><<<(total + 511) / 512, 512>>>(support, esrc, edst, ew, agg, total);
    }
    {
        int total = NN * 64 / 4;
        bias_relu_zero_kernel<<<(total + 255) / 256, 256>>>(agg, b1, l1, 16, total);
        // agg[0 .. NN*64) is now zero again -> L2 scatter needs no memset
    }

    // ---- Layer 2 (scatter first, 64 ch): l2 = relu((A l1) @ W2 + b2) ----
    {
        int total = NE << 3;
        scatter_kernel<3, 8><<<(total + 511) / 512, 512>>>(l1, esrc, edst, ew, agg, total);
    }
    gemm128_kernel<<<dim3(1, MB128), 256>>>(agg, W2, b2, l2, NN, 64, 128, 1);

    // ---- Layer 3 (scatter first, 128 ch): l3 = relu((A l2) @ W3 + b3) ----
    cudaMemsetAsync(agg, 0, (size_t)NN * 128 * sizeof(float));
    {
        int total = NE << 3;   // D=128: SHIFT=3, NF=16
        scatter_kernel<3, 16><<<(total + 511) / 512, 512>>>(l2, esrc, edst, ew, agg, total);
    }
    gemm128_kernel<<<dim3(2, MB128), 256>>>(agg, W3, b3, l3, NN, 128, 256, 1);

    // ---- Layers 4-6: accumulate A-aggregates in place.
    //   agg = A l3                   -> l4 = relu(agg @ W4 + b4)
    //   agg += A l4  (= A(l4+l3))    -> l5 = relu(agg @ W5 + b5)
    //   agg += A l5  (= A(l5+l4+l3)) -> out = relu(agg @ W6 + b6)
    cudaMemsetAsync(agg, 0, (size_t)NN * 256 * sizeof(float));
    {
        int total = NE << 4;   // D=256: SHIFT=4, NF=16
        scatter_kernel<4, 16><<<(total + 511) / 512, 512>>>(l3, esrc, edst, ew, agg, total);
    }
    gemm128_kernel<<<dim3(2, MB128), 256>>>(agg, W4, b4, l4, NN, 256, 256, 1);

    {
        int total = NE << 4;
        scatter_kernel<4, 16><<<(total + 511) / 512, 512>>>(l4, esrc, edst, ew, agg, total);
    }
    gemm128_kernel<<<dim3(2, MB128), 256>>>(agg, W5, b5, l5, NN, 256, 256, 1);

    {
        int total = NE << 4;
        scatter_kernel<4, 16><<<(total + 511) / 512, 512>>>(l5, esrc, edst, ew, agg, total);
    }
    gemm128_kernel<<<dim3(2, MB128), 256>>>(agg, W6, b6, out, NN, 256, 256, 1);
}

// round 17
// speedup vs baseline: 1.2236x; 1.2236x over previous
#include <cuda_runtime.h>
#include <cstdint>

#define NN 50000
#define NE 300000

// ---------------- scratch (static __device__ arrays; no allocation) ----------------
__device__ float g_support[NN * 64];   // L1: x @ W1
__device__ float g_agg[NN * 256];      // aggregation buffer (accumulated across L4-L6)
__device__ float g_l1[NN * 64];
__device__ float g_l2[NN * 128];
__device__ float g_l3[NN * 256];
__device__ float g_l4[NN * 256];
__device__ float g_l5[NN * 256];
// CSR sort scratch
__device__ int   g_cnt[NN];        // per-dst degree
__device__ int   g_offs[NN + 1];   // CSR offsets
__device__ int   g_cursor[NN];     // fill cursors
__device__ int   g_src_s[NE];      // dst-sorted src ids
__device__ float g_w_s[NE];        // dst-sorted weights

// ---------------- packed f32x2 FMA (sm_100+) ----------------
__device__ __forceinline__ void ffma2(uint64_t& d, uint64_t a, uint64_t b)
{
    asm("fma.rn.f32x2 %0, %1, %2, %0;" : "+l"(d) : "l"(a), "l"(b));
}
__device__ __forceinline__ uint64_t pack_dup(float f)
{
    uint64_t r;
    asm("mov.b64 %0, {%1, %1};" : "=l"(r) : "r"(__float_as_uint(f)));
    return r;
}

// ---------------- big GEMM: 128x128 tile, 8x8 microtile, f32x2 FMA ----------------
__global__ __launch_bounds__(256)
void gemm128_kernel(const float* __restrict__ A, const float* __restrict__ B,
                    const float* __restrict__ bias, float* __restrict__ C,
                    int M, int K, int N, int fuse)
{
    __shared__ float As[2][16][132];
    __shared__ float Bs[2][16][132];

    const int tid = threadIdx.x;
    const int m0  = blockIdx.y * 128;
    const int n0  = blockIdx.x * 128;
    const int tx  = tid & 15;
    const int ty  = tid >> 4;

    const int a_m = tid >> 1;
    const int a_k = (tid & 1) * 8;
    const int b_k = tid >> 4;
    const int b_n = (tid & 15) * 8;

    const bool a_valid = (m0 + a_m) < M;
    const float* a_ptr = A + (long)(m0 + a_m) * K + a_k;
    const float* b_ptr = B + (long)b_k * N + n0 + b_n;

    uint64_t acc2[8][4];
    #pragma unroll
    for (int i = 0; i < 8; i++)
        #pragma unroll
        for (int j = 0; j < 4; j++) acc2[i][j] = 0ull;

    float4 pa0 = make_float4(0.f,0.f,0.f,0.f), pa1 = make_float4(0.f,0.f,0.f,0.f);
    float4 pb0, pb1;
    if (a_valid) {
        pa0 = *(const float4*)(a_ptr);
        pa1 = *(const float4*)(a_ptr + 4);
    }
    pb0 = *(const float4*)(b_ptr);
    pb1 = *(const float4*)(b_ptr + 4);

    int buf = 0;
    for (int k0 = 0; k0 < K; k0 += 16) {
        As[buf][a_k + 0][a_m] = pa0.x;  As[buf][a_k + 1][a_m] = pa0.y;
        As[buf][a_k + 2][a_m] = pa0.z;  As[buf][a_k + 3][a_m] = pa0.w;
        As[buf][a_k + 4][a_m] = pa1.x;  As[buf][a_k + 5][a_m] = pa1.y;
        As[buf][a_k + 6][a_m] = pa1.z;  As[buf][a_k + 7][a_m] = pa1.w;
        *(float4*)&Bs[buf][b_k][b_n]     = pb0;
        *(float4*)&Bs[buf][b_k][b_n + 4] = pb1;
        __syncthreads();

        if (k0 + 16 < K) {
            const float* ap = a_ptr + (k0 + 16);
            const float* bp = b_ptr + (long)(k0 + 16) * N;
            if (a_valid) {
                pa0 = *(const float4*)(ap);
                pa1 = *(const float4*)(ap + 4);
            }
            pb0 = *(const float4*)(bp);
            pb1 = *(const float4*)(bp + 4);
        }

        #pragma unroll
        for (int k = 0; k < 16; k++) {
            float4 a0 = *(const float4*)&As[buf][k][ty * 4];
            float4 a1 = *(const float4*)&As[buf][k][64 + ty * 4];
            ulonglong2 b0 = *(const ulonglong2*)&Bs[buf][k][tx * 4];
            ulonglong2 b1 = *(const ulonglong2*)&Bs[buf][k][64 + tx * 4];
            uint64_t bb[4] = {b0.x, b0.y, b1.x, b1.y};
            float af[8] = {a0.x, a0.y, a0.z, a0.w, a1.x, a1.y, a1.z, a1.w};
            #pragma unroll
            for (int i = 0; i < 8; i++) {
                uint64_t ai = pack_dup(af[i]);
                #pragma unroll
                for (int j = 0; j < 4; j++)
                    ffma2(acc2[i][j], ai, bb[j]);
            }
        }
        buf ^= 1;
    }

    #pragma unroll
    for (int i = 0; i < 8; i++) {
        int row = m0 + ((i < 4) ? (ty * 4 + i) : (64 + ty * 4 + i - 4));
        if (row >= M) continue;
        #pragma unroll
        for (int h = 0; h < 2; h++) {
            int col = n0 + ((h == 0) ? (tx * 4) : (64 + tx * 4));
            uint32_t lo0 = (uint32_t)(acc2[i][2*h + 0] & 0xFFFFFFFFu);
            uint32_t hi0 = (uint32_t)(acc2[i][2*h + 0] >> 32);
            uint32_t lo1 = (uint32_t)(acc2[i][2*h + 1] & 0xFFFFFFFFu);
            uint32_t hi1 = (uint32_t)(acc2[i][2*h + 1] >> 32);
            float4 o = make_float4(__uint_as_float(lo0), __uint_as_float(hi0),
                                   __uint_as_float(lo1), __uint_as_float(hi1));
            if (fuse) {
                float4 bs = *(const float4*)(bias + col);
                o.x = fmaxf(o.x + bs.x, 0.f);
                o.y = fmaxf(o.y + bs.y, 0.f);
                o.z = fmaxf(o.z + bs.z, 0.f);
                o.w = fmaxf(o.w + bs.w, 0.f);
            }
            *(float4*)(C + (long)row * N + col) = o;
        }
    }
}

// ---------------- small GEMM (layer 1): 64x64 tile, 4x4 microtile ----------------
__global__ void gemm64_kernel(const float* __restrict__ A, const float* __restrict__ B,
                              const float* __restrict__ bias, float* __restrict__ C,
                              int M, int K, int N, int fuse)
{
    __shared__ float As[16][68];
    __shared__ float Bs[16][68];

    const int tid = threadIdx.x;
    const int m0  = blockIdx.y * 64;
    const int n0  = blockIdx.x * 64;
    const int tx  = tid & 15;
    const int ty  = tid >> 4;

    const int a_m = tid >> 2;
    const int a_k = (tid & 3) * 4;
    const int b_k = tid >> 4;
    const int b_n = (tid & 15) * 4;

    float acc[4][4];
    #pragma unroll
    for (int i = 0; i < 4; i++)
        #pragma unroll
        for (int j = 0; j < 4; j++) acc[i][j] = 0.f;

    for (int k0 = 0; k0 < K; k0 += 16) {
        {
            int row = m0 + a_m;
            float4 av = make_float4(0.f, 0.f, 0.f, 0.f);
            if (row < M)
                av = *(const float4*)(A + (long)row * K + k0 + a_k);
            As[a_k + 0][a_m] = av.x;
            As[a_k + 1][a_m] = av.y;
            As[a_k + 2][a_m] = av.z;
            As[a_k + 3][a_m] = av.w;
        }
        {
            float4 bv = *(const float4*)(B + (long)(k0 + b_k) * N + n0 + b_n);
            *(float4*)&Bs[b_k][b_n] = bv;
        }
        __syncthreads();

        #pragma unroll
        for (int k = 0; k < 16; k++) {
            float4 a = *(const float4*)&As[k][ty * 4];
            float4 b = *(const float4*)&Bs[k][tx * 4];
            float ar[4] = {a.x, a.y, a.z, a.w};
            float br[4] = {b.x, b.y, b.z, b.w};
            #pragma unroll
            for (int i = 0; i < 4; i++)
                #pragma unroll
                for (int j = 0; j < 4; j++)
                    acc[i][j] += ar[i] * br[j];
        }
        __syncthreads();
    }

    #pragma unroll
    for (int i = 0; i < 4; i++) {
        int row = m0 + ty * 4 + i;
        if (row >= M) continue;
        float4 o;
        float* po = (float*)&o;
        #pragma unroll
        for (int j = 0; j < 4; j++) {
            float v = acc[i][j];
            if (fuse) {
                v += __ldg(&bias[n0 + tx * 4 + j]);
                v = fmaxf(v, 0.f);
            }
            po[j] = v;
        }
        *(float4*)(C + (long)row * N + n0 + tx * 4) = o;
    }
}

// ================= dst-sorted CSR build (once per launch, reused 6x) =================

__global__ void hist_kernel(const int* __restrict__ dst, int* __restrict__ cnt)
{
    int e = blockIdx.x * blockDim.x + threadIdx.x;
    if (e < NE) atomicAdd(&cnt[dst[e]], 1);
}

// single block, 1024 threads: exclusive scan of cnt -> offs, init cursor.
__global__ void scan_kernel(const int* __restrict__ cnt, int* __restrict__ offs,
                            int* __restrict__ cursor)
{
    __shared__ int part[1024];
    const int tid = threadIdx.x;
    const int CH = (NN + 1023) / 1024;   // 49
    int beg = tid * CH;
    int end = beg + CH; if (end > NN) end = NN;
    if (beg > NN) beg = NN;

    int ssum = 0;
    for (int i = beg; i < end; i++) ssum += cnt[i];
    part[tid] = ssum;
    __syncthreads();

    // Hillis-Steele inclusive scan over part[]
    for (int off = 1; off < 1024; off <<= 1) {
        int add = (tid >= off) ? part[tid - off] : 0;
        __syncthreads();
        part[tid] += add;
        __syncthreads();
    }

    int running = part[tid] - ssum;   // exclusive prefix of this chunk
    for (int i = beg; i < end; i++) {
        offs[i] = running;
        cursor[i] = running;
        running += cnt[i];
    }
    if (tid == 1023) offs[NN] = part[1023];
}

__global__ void permute_kernel(const int* __restrict__ src, const int* __restrict__ dst,
                               const float* __restrict__ w,
                               int* __restrict__ cursor,
                               int* __restrict__ src_s, float* __restrict__ w_s)
{
    int e = blockIdx.x * blockDim.x + threadIdx.x;
    if (e >= NE) return;
    int d = dst[e];
    int pos = atomicAdd(&cursor[d], 1);
    src_s[pos] = src[e];
    w_s[pos] = w[e];
}

// ================= gather-based aggregation =================
// MODE 0: out = sum ; MODE 1: out = relu(sum + bias) ; MODE 2: out += sum
// TPN = D/NF threads per node; each thread owns NF contiguous channels, accumulates in registers.
// Edge loop processes 2 edges/iteration for MLP.
template<int D, int NF, int MODE>
__global__ void gather_kernel(const float* __restrict__ s0,
                              const int* __restrict__ src_s, const float* __restrict__ w_s,
                              const int* __restrict__ offs,
                              const float* __restrict__ bias,
                              float* __restrict__ outp)
{
    constexpr int TPN = D / NF;
    int t = blockIdx.x * blockDim.x + threadIdx.x;
    int n = t / TPN;
    if (n >= NN) return;
    int c = (t % TPN) * NF;

    int j   = __ldg(&offs[n]);
    int end = __ldg(&offs[n + 1]);

    float acc[NF];
    if (MODE == 2) {
        const float* pa = outp + (long)n * D + c;
        #pragma unroll
        for (int i = 0; i < NF / 4; i++) {
            float4 v = *(const float4*)(pa + 4 * i);
            acc[4*i+0] = v.x; acc[4*i+1] = v.y; acc[4*i+2] = v.z; acc[4*i+3] = v.w;
        }
    } else {
        #pragma unroll
        for (int i = 0; i < NF; i++) acc[i] = 0.f;
    }

    // 2 edges per iteration: both metadata loads, then both feature loads -> 2x MLP
    for (; j + 1 < end; j += 2) {
        int   sA = __ldg(&src_s[j]);
        int   sB = __ldg(&src_s[j + 1]);
        float wA = __ldg(&w_s[j]);
        float wB = __ldg(&w_s[j + 1]);
        const float* pA = s0 + (long)sA * D + c;
        const float* pB = s0 + (long)sB * D + c;
        float4 vA[NF / 4], vB[NF / 4];
        #pragma unroll
        for (int i = 0; i < NF / 4; i++) vA[i] = *(const float4*)(pA + 4 * i);
        #pragma unroll
        for (int i = 0; i < NF / 4; i++) vB[i] = *(const float4*)(pB + 4 * i);
        #pragma unroll
        for (int i = 0; i < NF / 4; i++) {
            acc[4*i+0] += wA * vA[i].x + wB * vB[i].x;
            acc[4*i+1] += wA * vA[i].y + wB * vB[i].y;
            acc[4*i+2] += wA * vA[i].z + wB * vB[i].z;
            acc[4*i+3] += wA * vA[i].w + wB * vB[i].w;
        }
    }
    if (j < end) {
        int   s = __ldg(&src_s[j]);
        float wt = __ldg(&w_s[j]);
        const float* ps = s0 + (long)s * D + c;
        #pragma unroll
        for (int i = 0; i < NF / 4; i++) {
            float4 v = *(const float4*)(ps + 4 * i);
            acc[4*i+0] += wt * v.x;
            acc[4*i+1] += wt * v.y;
            acc[4*i+2] += wt * v.z;
            acc[4*i+3] += wt * v.w;
        }
    }

    if (MODE == 1) {
        #pragma unroll
        for (int i = 0; i < NF; i++)
            acc[i] = fmaxf(acc[i] + __ldg(&bias[c + i]), 0.f);
    }

    float* po = outp + (long)n * D + c;
    #pragma unroll
    for (int i = 0; i < NF / 4; i++)
        *(float4*)(po + 4 * i) = make_float4(acc[4*i+0], acc[4*i+1], acc[4*i+2], acc[4*i+3]);
}

// ---------------- launch ----------------
extern "C" void kernel_launch(void* const* d_in, const int* in_sizes, int n_in,
                              void* d_out, int out_size)
{
    const float* x    = (const float*)d_in[0];
    const int*   esrc = (const int*)d_in[1];
    const int*   edst = (const int*)d_in[2];
    const float* ew   = (const float*)d_in[3];
    const float* W1 = (const float*)d_in[4];  const float* b1 = (const float*)d_in[5];
    const float* W2 = (const float*)d_in[6];  const float* b2 = (const float*)d_in[7];
    const float* W3 = (const float*)d_in[8];  const float* b3 = (const float*)d_in[9];
    const float* W4 = (const float*)d_in[10]; const float* b4 = (const float*)d_in[11];
    const float* W5 = (const float*)d_in[12]; const float* b5 = (const float*)d_in[13];
    const float* W6 = (const float*)d_in[14]; const float* b6 = (const float*)d_in[15];
    float* out = (float*)d_out;

    float *support, *agg, *l1, *l2, *l3, *l4, *l5;
    int *cnt, *offs, *cursor, *src_s;
    float *w_s;
    cudaGetSymbolAddress((void**)&support, g_support);
    cudaGetSymbolAddress((void**)&agg, g_agg);
    cudaGetSymbolAddress((void**)&l1, g_l1);
    cudaGetSymbolAddress((void**)&l2, g_l2);
    cudaGetSymbolAddress((void**)&l3, g_l3);
    cudaGetSymbolAddress((void**)&l4, g_l4);
    cudaGetSymbolAddress((void**)&l5, g_l5);
    cudaGetSymbolAddress((void**)&cnt, g_cnt);
    cudaGetSymbolAddress((void**)&offs, g_offs);
    cudaGetSymbolAddress((void**)&cursor, g_cursor);
    cudaGetSymbolAddress((void**)&src_s, g_src_s);
    cudaGetSymbolAddress((void**)&w_s, g_w_s);

    const int MB64  = (NN + 63) / 64;    // 782
    const int MB128 = (NN + 127) / 128;  // 391

    // ---- build dst-sorted CSR (reused by all 6 aggregations) ----
    cudaMemsetAsync(cnt, 0, NN * sizeof(int));
    hist_kernel<<<(NE + 255) / 256, 256>>>(edst, cnt);
    scan_kernel<<<1, 1024>>>(cnt, offs, cursor);
    permute_kernel<<<(NE + 255) / 256, 256>>>(esrc, edst, ew, cursor, src_s, w_s);

    // ---- Layer 1 (GEMM first, aggregate 64ch): l1 = relu(A(x W1) + b1) ----
    gemm64_kernel<<<dim3(1, MB64), 256>>>(x, W1, nullptr, support, NN, 128, 64, 0);
    {
        int threads = NN * 16;   // D=64, NF=4, TPN=16
        gather_kernel<64, 4, 1><<<(threads + 255) / 256, 256>>>(support, src_s, w_s, offs, b1, l1);
    }

    // ---- Layer 2: l2 = relu((A l1) @ W2 + b2) ----
    {
        int threads = NN * 16;
        gather_kernel<64, 4, 0><<<(threads + 255) / 256, 256>>>(l1, src_s, w_s, offs, nullptr, agg);
    }
    gemm128_kernel<<<dim3(1, MB128), 256>>>(agg, W2, b2, l2, NN, 64, 128, 1);

    // ---- Layer 3: l3 = relu((A l2) @ W3 + b3) ----
    {
        int threads = NN * 16;   // D=128, NF=8, TPN=16
        gather_kernel<128, 8, 0><<<(threads + 255) / 256, 256>>>(l2, src_s, w_s, offs, nullptr, agg);
    }
    gemm128_kernel<<<dim3(2, MB128), 256>>>(agg, W3, b3, l3, NN, 128, 256, 1);

    // ---- Layers 4-6: in-place CSR aggregation (agg accumulates A l3, +A l4, +A l5) ----
    {
        int threads = NN * 32;   // D=256, NF=8, TPN=32
        gather_kernel<256, 8, 0><<<(threads + 255) / 256, 256>>>(l3, src_s, w_s, offs, nullptr, agg);
    }
    gemm128_kernel<<<dim3(2, MB128), 256>>>(agg, W4, b4, l4, NN, 256, 256, 1);

    {
        int threads = NN * 32;
        gather_kernel<256, 8, 2><<<(threads + 255) / 256, 256>>>(l4, src_s, w_s, offs, nullptr, agg);
    }
    gemm128_kernel<<<dim3(2, MB128), 256>>>(agg, W5, b5, l5, NN, 256, 256, 1);

    {
        int threads = NN * 32;
        gather_kernel<256, 8, 2><<<(threads + 255) / 256, 256>>>(l5, src_s, w_s, offs, nullptr, agg);
    }
    gemm128_kernel<<<dim3(2, MB128), 256>>>(agg, W6, b6, out, NN, 256, 256, 1);
}